// round 2
// baseline (speedup 1.0000x reference)
#include <cuda_runtime.h>

#define RR 4
#define ND 81
#define HH 128
#define WW 256
#define CC 128
#define BB 8

#define HT 8                 // tile height
#define WT 32                // tile width
#define PW 8                 // pixels per thread (w)
#define CB 4                 // channels per stage
#define NCHUNK (CC/CB)       // 32
#define WROWS (HT + 2*RR)    // 16 warped rows per channel
#define WROW 44              // warped row stride (floats); 40 used, 44%4==0, 44%32==12 -> conflict-free
#define XROW 36              // x row stride (floats); 32 used
#define WCH (WROWS*WROW)     // 704
#define XCH (HT*XROW)        // 288
#define CHSZ (WCH + XCH)     // 992
#define STG (CB*CHSZ)        // 3968 floats per stage
#define NTHR 288             // 9 di * 8 h * 4 wgroups

typedef unsigned long long u64t;

static __device__ __forceinline__ u64t pk2(float lo, float hi) {
    return __double_as_longlong(__hiloint2double(__float_as_int(hi), __float_as_int(lo)));
}
static __device__ __forceinline__ void fma2(u64t &acc, u64t a, u64t b) {
    asm("fma.rn.f32x2 %0, %1, %2, %0;" : "+l"(acc) : "l"(a), "l"(b));
}
static __device__ __forceinline__ float lo32(u64t v) {
    return __int_as_float(__double2loint(__longlong_as_double(v)));
}
static __device__ __forceinline__ float hi32(u64t v) {
    return __int_as_float(__double2hiint(__longlong_as_double(v)));
}
static __device__ __forceinline__ void cpa16(unsigned dst, const float* src) {
    asm volatile("cp.async.cg.shared.global [%0], [%1], 16;" :: "r"(dst), "l"(src));
}
static __device__ __forceinline__ void cpa4(unsigned dst, const float* src) {
    asm volatile("cp.async.ca.shared.global [%0], [%1], 4;" :: "r"(dst), "l"(src));
}

__global__ void __launch_bounds__(NTHR, 2)
cost_volume_kernel(const float* __restrict__ gx, const float* __restrict__ gw,
                   float* __restrict__ gout)
{
    __shared__ __align__(16) float smf[2 * STG];

    const int tid = threadIdx.x;
    const int w0  = blockIdx.x * WT;
    const int h0  = blockIdx.y * HT;
    const int b   = blockIdx.z;

    const float* xb = gx + (size_t)b * CC * HH * WW;
    const float* wb = gw + (size_t)b * CC * HH * WW;
    const unsigned smb = (unsigned)__cvta_generic_to_shared(smf);

    // stage CB channels of (warped halo tile + x tile) into buffer s
    auto do_stage = [&](int chunk, int s) {
        if (chunk < NCHUNK) {
            #pragma unroll
            for (int cc2 = 0; cc2 < CB; cc2++) {
                const int c = chunk * CB + cc2;
                const float* wc = wb + (size_t)c * HH * WW;
                const float* xc = xb + (size_t)c * HH * WW;
                float* smw = smf + s * STG + cc2 * CHSZ;
                const unsigned sbase = smb + (unsigned)((s * STG + cc2 * CHSZ) * 4);

                // warped interior: 16 rows x 8 float4 = cols [w0, w0+32)
                if (tid < 128) {
                    const int row = tid >> 3, c4 = tid & 7;
                    const int gh  = h0 - RR + row;
                    const int off = row * WROW + RR + c4 * 4;
                    if ((unsigned)gh < HH)
                        cpa16(sbase + (unsigned)(off * 4), wc + gh * WW + w0 + c4 * 4);
                    else
                        *(float4*)(smw + off) = make_float4(0.f, 0.f, 0.f, 0.f);
                }
                // x tile: 8 rows x 8 float4 (always in range)
                if (tid >= 128 && tid < 192) {
                    const int i = tid - 128;
                    const int row = i >> 3, c4 = i & 7;
                    cpa16(sbase + (unsigned)((WCH + row * XROW + c4 * 4) * 4),
                          xc + (h0 + row) * WW + w0 + c4 * 4);
                }
                // warped edges: 16 rows x (4 left + 4 right) scalars
                if (tid >= 160) {
                    const int e = tid - 160;
                    const int row = e >> 3, k = e & 7;
                    const int gh   = h0 - RR + row;
                    const int gcol = (k < 4) ? (w0 - RR + k) : (w0 + WT + k - 4);
                    const int soff = (k < 4) ? k : (32 + k);
                    if ((unsigned)gh < HH && (unsigned)gcol < WW)
                        cpa4(sbase + (unsigned)((row * WROW + soff) * 4), wc + gh * WW + gcol);
                    else
                        smw[row * WROW + soff] = 0.0f;
                }
            }
        }
        asm volatile("cp.async.commit_group;" ::: "memory");
    };

    // thread -> (dj-range via window, fixed di, fixed h row, fixed w group)
    const int dig = tid % 9;        // di + 4
    const int hwg = tid / 9;        // 0..31
    const int h_i = hwg & 7;
    const int wg  = hwg >> 3;       // 0..3

    u64t acc[36];                   // [dj (9)][pixel-pair (4)]
    #pragma unroll
    for (int i = 0; i < 36; i++) acc[i] = 0ULL;

    do_stage(0, 0);
    do_stage(1, 1);

    for (int chunk = 0; chunk < NCHUNK; chunk++) {
        const int s = chunk & 1;
        asm volatile("cp.async.wait_group 1;" ::: "memory");
        __syncthreads();

        #pragma unroll
        for (int cc2 = 0; cc2 < CB; cc2++) {
            const float* base = smf + s * STG + cc2 * CHSZ;
            const float4* wv4 = (const float4*)(base + (h_i + dig) * WROW + wg * PW);
            const float4* xv4 = (const float4*)(base + WCH + h_i * XROW + wg * PW);

            float wr[16];
            #pragma unroll
            for (int k = 0; k < 4; k++) {
                float4 t = wv4[k];
                wr[4*k+0] = t.x; wr[4*k+1] = t.y; wr[4*k+2] = t.z; wr[4*k+3] = t.w;
            }
            float4 x0 = xv4[0], x1 = xv4[1];
            u64t xv[4];
            xv[0] = pk2(x0.x, x0.y); xv[1] = pk2(x0.z, x0.w);
            xv[2] = pk2(x1.x, x1.y); xv[3] = pk2(x1.z, x1.w);

            #pragma unroll
            for (int p = 0; p < 4; p++) {
                #pragma unroll
                for (int dj = 0; dj < 9; dj++) {
                    fma2(acc[dj * 4 + p], xv[p], pk2(wr[2*p + dj], wr[2*p + dj + 1]));
                }
            }
        }

        __syncthreads();
        do_stage(chunk + 2, s);
    }

    // epilogue: scale by 1/(C*81), write 9 dj planes x 8 pixels
    const float sc = 1.0f / (float)(CC * ND);
    float* ob = gout + (((size_t)b * ND + dig * 9) * HH + (h0 + h_i)) * WW + w0 + wg * PW;
    #pragma unroll
    for (int dj = 0; dj < 9; dj++) {
        float* od = ob + (size_t)dj * HH * WW;
        #pragma unroll
        for (int p = 0; p < 4; p++) {
            u64t v = acc[dj * 4 + p];
            float2 r;
            r.x = lo32(v) * sc;
            r.y = hi32(v) * sc;
            *(float2*)(od + 2 * p) = r;
        }
    }
}

extern "C" void kernel_launch(void* const* d_in, const int* in_sizes, int n_in,
                              void* d_out, int out_size) {
    const float* x = (const float*)d_in[0];
    const float* w = (const float*)d_in[1];
    float* out = (float*)d_out;
    dim3 grid(WW / WT, HH / HT, BB);   // (8, 16, 8) = 1024 blocks
    cost_volume_kernel<<<grid, NTHR>>>(x, w, out);
}